// round 16
// baseline (speedup 1.0000x reference)
#include <cuda_runtime.h>
#include <cuda_fp16.h>
#include <mma.h>

using namespace nvcuda;

#define BATCH   2
#define LSEQ    2048
#define DMODEL  1024
#define NHEADS  16
#define DKH     64
#define BHN     (BATCH * NHEADS)     // 32
#define BLM     (BATCH * LSEQ)       // 4096
#define TOPK    (LSEQ / 2)           // 1024
#define KSPLIT  3072                 // fp16x3 K-concat length
#define WSCALE  64.0f                // weight pre-scale
#define PSCALE  1024.0f              // prob pre-scale in attnv

// ---- scratch (static device arrays; allocation-free per harness rules) ----
__device__ float g_Q[(size_t)BLM * DMODEL];
__device__ float g_K[(size_t)BLM * DMODEL];
__device__ float g_V[(size_t)BLM * DMODEL];
__device__ float g_ctx[(size_t)BLM * DMODEL];
__device__ float g_S[(size_t)BHN * LSEQ * LSEQ];   // 537 MB scores
__device__ float4 g_rp[(size_t)BHN * LSEQ];        // per-row softmax params
__device__ __half g_A0[(size_t)BLM * KSPLIT];      // split activations (q / ctx)
__device__ __half g_A1[(size_t)BLM * KSPLIT];      // split activations (k)
__device__ __half g_A2[(size_t)BLM * KSPLIT];      // split activations (v)
__device__ __half g_B0[(size_t)DMODEL * KSPLIT];   // split Wq
__device__ __half g_B1[(size_t)DMODEL * KSPLIT];   // split Wk
__device__ __half g_B2[(size_t)DMODEL * KSPLIT];   // split Wv
__device__ __half g_B3[(size_t)DMODEL * KSPLIT];   // split Wo
__device__ float g_brep[4 * 16 * DMODEL];          // replicated bias tiles

// monotone float<->uint mapping (order-preserving)
__device__ __forceinline__ unsigned f2key(float f) {
    unsigned u = __float_as_uint(f);
    return (u & 0x80000000u) ? ~u : (u | 0x80000000u);
}
__device__ __forceinline__ float key2f(unsigned key) {
    unsigned u = (key & 0x80000000u) ? (key ^ 0x80000000u) : ~key;
    return __uint_as_float(u);
}

__device__ __forceinline__ void cp_async16(void* sptr, const void* gptr) {
    unsigned sa = (unsigned)__cvta_generic_to_shared(sptr);
    asm volatile("cp.async.cg.shared.global [%0], [%1], 16;" :: "r"(sa), "l"(gptr));
}
__device__ __forceinline__ void cp_commit() {
    asm volatile("cp.async.commit_group;" ::: "memory");
}
__device__ __forceinline__ void cp_wait2() {
    asm volatile("cp.async.wait_group 2;" ::: "memory");
}
__device__ __forceinline__ void cp_wait1() {
    asm volatile("cp.async.wait_group 1;" ::: "memory");
}
__device__ __forceinline__ void cp_wait0() {
    asm volatile("cp.async.wait_group 0;" ::: "memory");
}

// ============================================================
// fp16x3 splits. X row -> [ah|ah|al]; W row (xWSCALE) -> [bh|bl|bh]
// ============================================================
__device__ __forceinline__ void split_x_body(
    const float* __restrict__ X, __half* __restrict__ O)
{
    int i = blockIdx.x * 256 + threadIdx.x;
    int r = i >> 10, c = i & 1023;
    float a = X[i];
    __half ah = __float2half(a);
    __half al = __float2half(a - __half2float(ah));
    __half* o = O + (size_t)r * KSPLIT;
    o[c] = ah; o[1024 + c] = ah; o[2048 + c] = al;
}
__global__ __launch_bounds__(256) void split_x3_kernel(
    const float* x0, const float* x1, const float* x2)
{
    const float* X = (blockIdx.z == 0) ? x0 : (blockIdx.z == 1) ? x1 : x2;
    __half* O = (blockIdx.z == 0) ? g_A0 : (blockIdx.z == 1) ? g_A1 : g_A2;
    split_x_body(X, O);
}
__global__ __launch_bounds__(256) void split_x1_kernel(const float* x0)
{
    split_x_body(x0, g_A0);
}
__global__ __launch_bounds__(256) void split_w4_kernel(
    const float* w0, const float* w1, const float* w2, const float* w3)
{
    const float* W = (blockIdx.z == 0) ? w0 : (blockIdx.z == 1) ? w1
                   : (blockIdx.z == 2) ? w2 : w3;
    __half* O = (blockIdx.z == 0) ? g_B0 : (blockIdx.z == 1) ? g_B1
              : (blockIdx.z == 2) ? g_B2 : g_B3;
    int i = blockIdx.x * 256 + threadIdx.x;
    int r = i >> 10, c = i & 1023;
    float b = W[i] * WSCALE;
    __half bh = __float2half(b);
    __half bl = __float2half(b - __half2float(bh));
    __half* o = O + (size_t)r * KSPLIT;
    o[c] = bh; o[1024 + c] = bl; o[2048 + c] = bh;
}
__global__ __launch_bounds__(256) void biasrep_kernel(
    const float* b0, const float* b1, const float* b2, const float* b3)
{
    const float* B = (blockIdx.z == 0) ? b0 : (blockIdx.z == 1) ? b1
                   : (blockIdx.z == 2) ? b2 : b3;
    int i = blockIdx.x * 256 + threadIdx.x;   // 0..16383
    g_brep[blockIdx.z * 16 * DMODEL + i] = B[i & 1023];
}

// ============================================================
// WMMA projection GEMM: Y = (X @ (WSCALE*W)^T)/WSCALE + bias
// CTA 128x128, 8 warps (2x4), warp 64x32. BK=32, cp.async 4-stage
// pipeline in dynamic smem, ONE __syncthreads per stage.
// Per-acc mma chain: same ascending K=16 sequence (bit-identical).
// ============================================================
#define MST    40
#define NPIPE  4
#define STAGE_H (128 * MST)                       // halves per stage per matrix
#define MM_DSMEM (2 * NPIPE * STAGE_H * 2)        // bytes = 81920

__device__ __forceinline__ void mm_body(
    const __half* __restrict__ A, const __half* __restrict__ Bm,
    const float* __restrict__ brep, float* __restrict__ Y,
    __half* __restrict__ As, __half* __restrict__ Bs)
{
    const int tid = threadIdx.x;
    const int wid = tid >> 5;
    const int wr = wid >> 2;           // 0..1 -> rows wr*64
    const int wc = wid & 3;            // 0..3 -> cols wc*32
    const int m0 = blockIdx.y * 128, n0 = blockIdx.x * 128;

    const int lr = tid >> 1;           // 0..127
    const int lu = (tid & 1) * 16;     // 0 or 16 halves (32 B)
    const __half* Ab = A + (size_t)(m0 + lr) * KSPLIT + lu;
    const __half* Bb = Bm + (size_t)(n0 + lr) * KSPLIT + lu;

    const int NST = KSPLIT / 32;       // 96 stages

    // prologue: stages 0..2 in flight
#pragma unroll
    for (int s = 0; s < NPIPE - 1; s++) {
        __half* as = As + s * STAGE_H + lr * MST + lu;
        __half* bs = Bs + s * STAGE_H + lr * MST + lu;
        cp_async16(as, Ab + s * 32);
        cp_async16(as + 8, Ab + s * 32 + 8);
        cp_async16(bs, Bb + s * 32);
        cp_async16(bs + 8, Bb + s * 32 + 8);
        cp_commit();
    }

    wmma::fragment<wmma::accumulator, 16, 16, 16, float> acc[4][2];
#pragma unroll
    for (int i = 0; i < 4; i++)
#pragma unroll
        for (int j = 0; j < 2; j++)
            wmma::fill_fragment(acc[i][j], 0.0f);

    for (int s = 0; s < NST; s++) {
        const int rem = NST - 1 - s;   // groups committed after stage s
        if (rem >= 2) cp_wait2();
        else if (rem == 1) cp_wait1();
        else cp_wait0();
        __syncthreads();
        // prefetch stage s+3 into buffer (s+3)%4 (last read at stage s-1; safe)
        if (s + NPIPE - 1 < NST) {
            const int nb = (s + NPIPE - 1) & (NPIPE - 1);
            int ko = (s + NPIPE - 1) * 32;
            __half* as = As + nb * STAGE_H + lr * MST + lu;
            __half* bs = Bs + nb * STAGE_H + lr * MST + lu;
            cp_async16(as, Ab + ko);
            cp_async16(as + 8, Ab + ko + 8);
            cp_async16(bs, Bb + ko);
            cp_async16(bs + 8, Bb + ko + 8);
            cp_commit();
        }
        const int buf = s & (NPIPE - 1);
        const __half* Asb = As + buf * STAGE_H;
        const __half* Bsb = Bs + buf * STAGE_H;
#pragma unroll
        for (int kk = 0; kk < 32; kk += 16) {
            wmma::fragment<wmma::matrix_b, 16, 16, 16, __half, wmma::col_major> bf[2];
#pragma unroll
            for (int j = 0; j < 2; j++)
                wmma::load_matrix_sync(bf[j], Bsb + (wc * 32 + j * 16) * MST + kk, MST);
#pragma unroll
            for (int i = 0; i < 4; i++) {
                wmma::fragment<wmma::matrix_a, 16, 16, 16, __half, wmma::row_major> af;
                wmma::load_matrix_sync(af, Asb + (wr * 64 + i * 16) * MST + kk, MST);
#pragma unroll
                for (int j = 0; j < 2; j++)
                    wmma::mma_sync(acc[i][j], af, bf[j], acc[i][j]);
            }
        }
    }

    const float inv = 1.0f / WSCALE;
#pragma unroll
    for (int i = 0; i < 4; i++)
#pragma unroll
        for (int j = 0; j < 2; j++) {
            wmma::fragment<wmma::accumulator, 16, 16, 16, float> bfr;
            wmma::load_matrix_sync(bfr, brep + n0 + wc * 32 + j * 16, DMODEL,
                                   wmma::mem_row_major);
#pragma unroll
            for (int e = 0; e < acc[i][j].num_elements; e++)
                acc[i][j].x[e] = acc[i][j].x[e] * inv + bfr.x[e];
            wmma::store_matrix_sync(
                Y + (size_t)(m0 + wr * 64 + i * 16) * DMODEL + n0 + wc * 32 + j * 16,
                acc[i][j], DMODEL, wmma::mem_row_major);
        }
}
__global__ __launch_bounds__(256) void mm_qkv_kernel()
{
    extern __shared__ __align__(16) __half dynsm[];
    __half* As = dynsm;
    __half* Bs = dynsm + NPIPE * STAGE_H;
    if (blockIdx.z == 0)      mm_body(g_A0, g_B0, g_brep + 0 * 16 * DMODEL, g_Q, As, Bs);
    else if (blockIdx.z == 1) mm_body(g_A1, g_B1, g_brep + 1 * 16 * DMODEL, g_K, As, Bs);
    else                      mm_body(g_A2, g_B2, g_brep + 2 * 16 * DMODEL, g_V, As, Bs);
}
__global__ __launch_bounds__(256) void mm_out_kernel(float* __restrict__ Y)
{
    extern __shared__ __align__(16) __half dynsm[];
    __half* As = dynsm;
    __half* Bs = dynsm + NPIPE * STAGE_H;
    mm_body(g_A0, g_B3, g_brep + 3 * 16 * DMODEL, Y, As, Bs);
}

// ============================================================
// Scores (wmma, inline fp16x3): S[bh][q][k] = (Q . K) / 8  (unchanged)
// ============================================================
__global__ __launch_bounds__(256) void scores_wmma_kernel()
{
    __shared__ __align__(16) __half Qh[128][40], Ql[128][40];
    __shared__ __align__(16) __half Kh[128][40], Kl[128][40];
    const int tid = threadIdx.x;
    const int wid = tid >> 5;
    const int wr = wid >> 2;
    const int wc = wid & 3;
    const int bh = blockIdx.z, b = bh >> 4, h = bh & 15;
    const int q0 = blockIdx.y * 128, k0 = blockIdx.x * 128;
    const float* Qb = g_Q + (size_t)(b * LSEQ + q0) * DMODEL + h * DKH;
    const float* Kb = g_K + (size_t)(b * LSEQ + k0) * DMODEL + h * DKH;

    wmma::fragment<wmma::accumulator, 16, 16, 16, float> acc[4][2];
#pragma unroll
    for (int i = 0; i < 4; i++)
#pragma unroll
        for (int j = 0; j < 2; j++)
            wmma::fill_fragment(acc[i][j], 0.0f);

    for (int kc = 0; kc < DKH; kc += 32) {
#pragma unroll
        for (int it = 0; it < 4; it++) {
            int f = tid + 256 * it;
            int r = f >> 3, c4 = (f & 7) * 4;
            float4 qv = *(const float4*)(Qb + (size_t)r * DMODEL + kc + c4);
            float4 kv = *(const float4*)(Kb + (size_t)r * DMODEL + kc + c4);
            float qa[4] = {qv.x, qv.y, qv.z, qv.w};
            float ka[4] = {kv.x, kv.y, kv.z, kv.w};
#pragma unroll
            for (int e = 0; e < 4; e++) {
                __half qh = __float2half(qa[e]);
                Qh[r][c4 + e] = qh;
                Ql[r][c4 + e] = __float2half(qa[e] - __half2float(qh));
                __half kh = __float2half(ka[e]);
                Kh[r][c4 + e] = kh;
                Kl[r][c4 + e] = __float2half(ka[e] - __half2float(kh));
            }
        }
        __syncthreads();
#pragma unroll
        for (int kk = 0; kk < 32; kk += 16) {
            wmma::fragment<wmma::matrix_b, 16, 16, 16, __half, wmma::col_major> bh_f[2], bl_f[2];
#pragma unroll
            for (int j = 0; j < 2; j++) {
                wmma::load_matrix_sync(bh_f[j], &Kh[wc * 32 + j * 16][kk], 40);
                wmma::load_matrix_sync(bl_f[j], &Kl[wc * 32 + j * 16][kk], 40);
            }
#pragma unroll
            for (int i = 0; i < 4; i++) {
                wmma::fragment<wmma::matrix_a, 16, 16, 16, __half, wmma::row_major> ah_f, al_f;
                wmma::load_matrix_sync(ah_f, &Qh[wr * 64 + i * 16][kk], 40);
                wmma::load_matrix_sync(al_f, &Ql[wr * 64 + i * 16][kk], 40);
#pragma unroll
                for (int j = 0; j < 2; j++) {
                    wmma::mma_sync(acc[i][j], ah_f, bh_f[j], acc[i][j]);
                    wmma::mma_sync(acc[i][j], ah_f, bl_f[j], acc[i][j]);
                    wmma::mma_sync(acc[i][j], al_f, bh_f[j], acc[i][j]);
                }
            }
        }
        __syncthreads();
    }
    float* Sb = g_S + (size_t)bh * LSEQ * LSEQ;
#pragma unroll
    for (int i = 0; i < 4; i++)
#pragma unroll
        for (int j = 0; j < 2; j++) {
#pragma unroll
            for (int e = 0; e < acc[i][j].num_elements; e++)
                acc[i][j].x[e] *= 0.125f;
            wmma::store_matrix_sync(
                Sb + (size_t)(q0 + wr * 64 + i * 16) * LSEQ + k0 + wc * 32 + j * 16,
                acc[i][j], LSEQ, wmma::mem_row_major);
        }
}

// ============================================================
// Per-row top-k threshold + softmax params (unchanged)
// ============================================================
__global__ __launch_bounds__(256) void topk_softmax_kernel()
{
    __shared__ unsigned keys[LSEQ];
    __shared__ unsigned hist[256];
    __shared__ unsigned warp_u[8];
    __shared__ float    warp_f[8];
    __shared__ unsigned s_sel, s_kkn, s_max, s_eq;
    __shared__ float    s_sum;

    const int tid  = threadIdx.x;
    const int lane = tid & 31, wid = tid >> 5;
    float* __restrict__ srow = g_S + (size_t)blockIdx.x * LSEQ;

    unsigned lmax = 0;
    for (int i = tid; i < LSEQ; i += 256) {
        unsigned key = f2key(srow[i]);
        keys[i] = key;
        lmax = key > lmax ? key : lmax;
    }
#pragma unroll
    for (int off = 16; off > 0; off >>= 1) {
        unsigned o = __shfl_xor_sync(0xffffffffu, lmax, off);
        lmax = o > lmax ? o : lmax;
    }
    if (lane == 0) warp_u[wid] = lmax;
    __syncthreads();
    if (tid == 0) {
        unsigned m = warp_u[0];
#pragma unroll
        for (int w = 1; w < 8; w++) m = warp_u[w] > m ? warp_u[w] : m;
        s_max = m;
    }
    __syncthreads();
    const unsigned maxkey = s_max;

    unsigned prefix = 0;
    unsigned kneed  = TOPK;
    for (int shift = 24; shift >= 0; shift -= 8) {
        hist[tid] = 0;
        __syncthreads();
        unsigned mask_hi = (shift == 24) ? 0u : (0xFFFFFFFFu << (shift + 8));
        for (int i = tid; i < LSEQ; i += 256) {
            unsigned key = keys[i];
            if ((key & mask_hi) == prefix)
                atomicAdd(&hist[(key >> shift) & 0xFFu], 1u);
        }
        __syncthreads();
        const unsigned h = hist[tid];
        unsigned v = h;
#pragma unroll
        for (int off = 1; off < 32; off <<= 1) {
            unsigned t = __shfl_down_sync(0xffffffffu, v, off);
            if (lane + off < 32) v += t;
        }
        if (lane == 0) warp_u[wid] = v;
        __syncthreads();
        unsigned wtail = 0;
#pragma unroll
        for (int w = 0; w < 8; w++) if (w > wid) wtail += warp_u[w];
        const unsigned sufi = v + wtail;
        const unsigned sufn = sufi - h;
        if (sufi >= kneed && sufn < kneed) {
            s_sel = (unsigned)tid;
            s_kkn = kneed - sufn;
        }
        __syncthreads();
        prefix |= (s_sel << shift);
        kneed = s_kkn;
    }
    const unsigned thr_key = prefix;
    const unsigned r = kneed;
    const float m    = key2f(maxkey);
    const float thrf = key2f(thr_key);

    float lsum = 0.f; unsigned leq = 0;
    for (int i = tid; i < LSEQ; i += 256) {
        unsigned key = keys[i];
        if (key > thr_key)       lsum += __expf(key2f(key) - m);
        else if (key == thr_key) leq++;
    }
#pragma unroll
    for (int off = 16; off > 0; off >>= 1) {
        lsum += __shfl_xor_sync(0xffffffffu, lsum, off);
        leq  += __shfl_xor_sync(0xffffffffu, leq,  off);
    }
    if (lane == 0) { warp_f[wid] = lsum; warp_u[wid] = leq; }
    __syncthreads();
    if (tid == 0) {
        float fs = 0.f; unsigned ue = 0;
#pragma unroll
        for (int w = 0; w < 8; w++) { fs += warp_f[w]; ue += warp_u[w]; }
        s_sum = fs; s_eq = ue;
    }
    __syncthreads();

    const float eth   = __expf(thrf - m);
    const float denom = s_sum + (float)r * eth;
    const float inv   = 1.0f / denom;
    const float peq   = eth * inv;
    const bool  fast  = (s_eq == r);

    if (fast) {
        if (tid == 0) g_rp[blockIdx.x] = make_float4(thrf, m, inv, peq);
    } else {
        for (int i = tid; i < LSEQ; i += 256) {
            unsigned key = keys[i];
            srow[i] = (key > thr_key) ? __expf(key2f(key) - m) * inv : 0.f;
        }
        __syncthreads();
        if (tid == 0) {
            unsigned cnt = 0;
            for (int i = 0; i < LSEQ; i++) {
                if (keys[i] == thr_key) {
                    if (cnt < r) srow[i] = peq;
                    cnt++;
                }
            }
            g_rp[blockIdx.x] = make_float4(0.f, 0.f, -1.f, 0.f);
        }
    }
}

// ============================================================
// attnv (wmma, inline softmax + fp16x3) (unchanged)
// ============================================================
__global__ __launch_bounds__(256) void attnv_wmma_kernel()
{
    __shared__ __align__(16) __half Ph[128][40], Pl[128][40];
    __shared__ __align__(16) __half Vh[32][72], Vl[32][72];
    const int tid = threadIdx.x;
    const int wid = tid >> 5;
    const int wr = wid >> 1;
    const int wc = wid & 1;
    const int bh = blockIdx.z, b = bh >> 4, h = bh & 15;
    const int m0 = blockIdx.x * 128;

    const float* Pb = g_S + (size_t)bh * LSEQ * LSEQ + (size_t)m0 * LSEQ;
    const float4* Rp = g_rp + (size_t)bh * LSEQ + m0;
    const float* Vb = g_V + (size_t)b * LSEQ * DMODEL + h * DKH;

    wmma::fragment<wmma::accumulator, 16, 16, 16, float> acc[2][2];
#pragma unroll
    for (int i = 0; i < 2; i++)
#pragma unroll
        for (int j = 0; j < 2; j++)
            wmma::fill_fragment(acc[i][j], 0.0f);

    for (int k0 = 0; k0 < LSEQ; k0 += 32) {
#pragma unroll
        for (int it = 0; it < 4; it++) {
            int f = tid + 256 * it;
            int r = f >> 3, c4 = (f & 7) * 4;
            float4 rp = Rp[r];
            float4 pv = *(const float4*)(Pb + (size_t)r * LSEQ + k0 + c4);
            float sa[4] = {pv.x, pv.y, pv.z, pv.w};
            float pa[4];
#pragma unroll
            for (int e = 0; e < 4; e++) {
                float s = sa[e];
                float p;
                if (rp.z < 0.f)       p = s;
                else if (s > rp.x)    p = __expf(s - rp.y) * rp.z;
                else if (s == rp.x)   p = rp.w;
                else                  p = 0.f;
                pa[e] = p * PSCALE;
            }
#pragma unroll
            for (int e = 0; e < 4; e++) {
                __half ph = __float2half(pa[e]);
                Ph[r][c4 + e] = ph;
                Pl[r][c4 + e] = __float2half(pa[e] - __half2float(ph));
            }
        }
#pragma unroll
        for (int it = 0; it < 2; it++) {
            int f = tid + 256 * it;
            int r = f >> 4, c4 = (f & 15) * 4;
            float4 vv = *(const float4*)(Vb + (size_t)(k0 + r) * DMODEL + c4);
            float va[4] = {vv.x, vv.y, vv.z, vv.w};
#pragma unroll
            for (int e = 0; e < 4; e++) {
                __half vh = __float2half(va[e]);
                Vh[r][c4 + e] = vh;
                Vl[r][c4 + e] = __float2half(va[e] - __half2float(vh));
            }
        }
        __syncthreads();
#pragma unroll
        for (int kk = 0; kk < 32; kk += 16) {
            wmma::fragment<wmma::matrix_b, 16, 16, 16, __half, wmma::row_major> bh_f[2], bl_f[2];
#pragma unroll
            for (int j = 0; j < 2; j++) {
                wmma::load_matrix_sync(bh_f[j], &Vh[kk][wc * 32 + j * 16], 72);
                wmma::load_matrix_sync(bl_f[j], &Vl[kk][wc * 32 + j * 16], 72);
            }
#pragma unroll
            for (int i = 0; i < 2; i++) {
                wmma::fragment<wmma::matrix_a, 16, 16, 16, __half, wmma::row_major> ah_f, al_f;
                wmma::load_matrix_sync(ah_f, &Ph[wr * 32 + i * 16][kk], 40);
                wmma::load_matrix_sync(al_f, &Pl[wr * 32 + i * 16][kk], 40);
#pragma unroll
                for (int j = 0; j < 2; j++) {
                    wmma::mma_sync(acc[i][j], ah_f, bh_f[j], acc[i][j]);
                    wmma::mma_sync(acc[i][j], ah_f, bl_f[j], acc[i][j]);
                    wmma::mma_sync(acc[i][j], al_f, bh_f[j], acc[i][j]);
                }
            }
        }
        __syncthreads();
    }
    float* Cb = g_ctx + (size_t)(b * LSEQ + m0) * DMODEL + h * DKH;
    const float inv = 1.0f / PSCALE;
#pragma unroll
    for (int i = 0; i < 2; i++)
#pragma unroll
        for (int j = 0; j < 2; j++) {
#pragma unroll
            for (int e = 0; e < acc[i][j].num_elements; e++)
                acc[i][j].x[e] *= inv;
            wmma::store_matrix_sync(
                Cb + (size_t)(wr * 32 + i * 16) * DMODEL + wc * 32 + j * 16,
                acc[i][j], DMODEL, wmma::mem_row_major);
        }
}

// ============================================================
extern "C" void kernel_launch(void* const* d_in, const int* in_sizes, int n_in,
                              void* d_out, int out_size)
{
    const float* q  = (const float*)d_in[0];
    const float* k  = (const float*)d_in[1];
    const float* v  = (const float*)d_in[2];
    const float* Wq = (const float*)d_in[3];
    const float* bq = (const float*)d_in[4];
    const float* Wk = (const float*)d_in[5];
    const float* bk = (const float*)d_in[6];
    const float* Wv = (const float*)d_in[7];
    const float* bv = (const float*)d_in[8];
    const float* Wo = (const float*)d_in[9];
    const float* bo = (const float*)d_in[10];
    float* out = (float*)d_out;

    static float* gC = nullptr;
    if (!gC) {
        cudaGetSymbolAddress((void**)&gC, g_ctx);
        cudaFuncSetAttribute(mm_qkv_kernel,
            cudaFuncAttributeMaxDynamicSharedMemorySize, MM_DSMEM);
        cudaFuncSetAttribute(mm_out_kernel,
            cudaFuncAttributeMaxDynamicSharedMemorySize, MM_DSMEM);
    }

    dim3 blk(256);
    const int NX = BLM * DMODEL;
    const int NW = DMODEL * DMODEL;

    // weight splits + bias replication (all 4 projections upfront)
    dim3 gsw(NW / 256, 1, 4);
    split_w4_kernel<<<gsw, blk>>>(Wq, Wk, Wv, Wo);
    dim3 gbr(16 * DMODEL / 256, 1, 4);
    biasrep_kernel<<<gbr, blk>>>(bq, bk, bv, bo);

    // q/k/v activation splits (one launch)
    dim3 gsx(NX / 256, 1, 3);
    split_x3_kernel<<<gsx, blk>>>(q, k, v);

    // QKV projections (one launch, 4-stage cp.async pipeline)
    dim3 gmm(DMODEL / 128, BLM / 128, 3);   // (8, 32, 3)
    mm_qkv_kernel<<<gmm, blk, MM_DSMEM>>>();

    dim3 gsc(LSEQ / 128, LSEQ / 128, BHN);  // (16, 16, 32)
    scores_wmma_kernel<<<gsc, blk>>>();

    topk_softmax_kernel<<<BHN * LSEQ, blk>>>();

    dim3 gav(LSEQ / 128, 1, BHN);           // (16, 1, 32)
    attnv_wmma_kernel<<<gav, blk>>>();

    // output projection
    dim3 gsx1(NX / 256);
    split_x1_kernel<<<gsx1, blk>>>(gC);
    dim3 gmo(DMODEL / 128, BLM / 128);
    mm_out_kernel<<<gmo, blk, MM_DSMEM>>>(out);
}